// round 1
// baseline (speedup 1.0000x reference)
#include <cuda_runtime.h>
#include <cstdint>
#include <math.h>

#define SA_N  8192
#define SA_D  1024
#define SA_DH 128

#define BM 64
#define BN 64
#define KPAD 132           // row stride (floats) for Qs/Ks/Vs tiles (128 + 4)
#define PPAD 68            // row stride (floats) for Ps tile (64 + 4)

#define QS_OFF 0
#define TILE_F (BM*KPAD)   // 8448 floats per 64x128 tile
#define KS_OFF (TILE_F)
#define VS_OFF (TILE_F*3)
#define PS_OFF (TILE_F*5)
#define SMEM_FLOATS (TILE_F*5 + BN*PPAD)
#define SMEM_BYTES (SMEM_FLOATS*4)   // 186368 bytes

// Scratch for projected Q (pre-scaled), K, V
__device__ float g_Q[SA_N*SA_DH];
__device__ float g_K[SA_N*SA_DH];
__device__ float g_V[SA_N*SA_DH];

__device__ __forceinline__ void cp_async16(uint32_t dst, const void* src) {
    asm volatile("cp.async.cg.shared.global [%0], [%1], 16;\n" :: "r"(dst), "l"(src));
}
__device__ __forceinline__ void cp_commit() {
    asm volatile("cp.async.commit_group;\n" ::);
}
__device__ __forceinline__ void cp_wait0() {
    asm volatile("cp.async.wait_group 0;\n" ::);
}

// ---------------------------------------------------------------------------
// Kernel 1: QKV projection. grid = (N/64, 3), block = 256.
// Y = x @ W, Q additionally scaled by 1/sqrt(128).
// ---------------------------------------------------------------------------
#define P1_BK 32
__global__ __launch_bounds__(256, 1)
void qkv_kernel(const float* __restrict__ x,
                const float* __restrict__ Wq,
                const float* __restrict__ Wk,
                const float* __restrict__ Wv) {
    __shared__ float Xs[64][P1_BK + 4];
    __shared__ float Ws[P1_BK][SA_DH + 4];

    const float* W;
    float* Y;
    float scale;
    if (blockIdx.y == 0)      { W = Wq; Y = g_Q; scale = 0.08838834764831845f; }
    else if (blockIdx.y == 1) { W = Wk; Y = g_K; scale = 1.0f; }
    else                      { W = Wv; Y = g_V; scale = 1.0f; }

    const int tid = threadIdx.x;
    const int ty = tid >> 4;      // 0..15 -> 4 rows each
    const int tx = tid & 15;      // 0..15 -> 8 cols each
    const int row0 = blockIdx.x * 64;

    float acc[4][8];
#pragma unroll
    for (int r = 0; r < 4; r++)
#pragma unroll
        for (int c = 0; c < 8; c++) acc[r][c] = 0.0f;

    for (int k0 = 0; k0 < SA_D; k0 += P1_BK) {
        __syncthreads();
        // Xs: 64 x 32 floats = 512 float4, 2 per thread
#pragma unroll
        for (int i = tid; i < 64 * 8; i += 256) {
            int r = i >> 3, c4 = i & 7;
            float4 v = *(const float4*)&x[(size_t)(row0 + r) * SA_D + k0 + c4 * 4];
            *(float4*)&Xs[r][c4 * 4] = v;
        }
        // Ws: 32 x 128 floats = 1024 float4, 4 per thread
#pragma unroll
        for (int i = tid; i < 32 * 32; i += 256) {
            int r = i >> 5, c4 = i & 31;
            float4 v = *(const float4*)&W[(size_t)(k0 + r) * SA_DH + c4 * 4];
            *(float4*)&Ws[r][c4 * 4] = v;
        }
        __syncthreads();

#pragma unroll
        for (int kk4 = 0; kk4 < 8; kk4++) {
            float xa[4][4];
#pragma unroll
            for (int rr = 0; rr < 4; rr++) {
                float4 q = *(float4*)&Xs[ty * 4 + rr][kk4 * 4];
                xa[rr][0] = q.x; xa[rr][1] = q.y; xa[rr][2] = q.z; xa[rr][3] = q.w;
            }
#pragma unroll
            for (int kk = 0; kk < 4; kk++) {
                float4 w0 = *(float4*)&Ws[kk4 * 4 + kk][tx * 8];
                float4 w1 = *(float4*)&Ws[kk4 * 4 + kk][tx * 8 + 4];
                float wv[8];
                wv[0] = w0.x; wv[1] = w0.y; wv[2] = w0.z; wv[3] = w0.w;
                wv[4] = w1.x; wv[5] = w1.y; wv[6] = w1.z; wv[7] = w1.w;
#pragma unroll
                for (int rr = 0; rr < 4; rr++)
#pragma unroll
                    for (int c = 0; c < 8; c++)
                        acc[rr][c] += xa[rr][kk] * wv[c];
            }
        }
    }

#pragma unroll
    for (int rr = 0; rr < 4; rr++) {
        size_t row = row0 + ty * 4 + rr;
        float4 o0, o1;
        o0.x = acc[rr][0] * scale; o0.y = acc[rr][1] * scale;
        o0.z = acc[rr][2] * scale; o0.w = acc[rr][3] * scale;
        o1.x = acc[rr][4] * scale; o1.y = acc[rr][5] * scale;
        o1.z = acc[rr][6] * scale; o1.w = acc[rr][7] * scale;
        *(float4*)&Y[row * SA_DH + tx * 8]     = o0;
        *(float4*)&Y[row * SA_DH + tx * 8 + 4] = o1;
    }
}

// ---------------------------------------------------------------------------
// Kernel 2: fused flash attention (fp32). grid = N/64 = 128, block = 256.
// One CTA owns BM=64 query rows, streams all K/V in BN=64 chunks with
// cp.async double buffering, online softmax.
// ---------------------------------------------------------------------------
__device__ __forceinline__ void load_kv_chunk(float* smem, int buf, int t, int tid) {
    uint32_t kdst = (uint32_t)__cvta_generic_to_shared(&smem[KS_OFF + buf * TILE_F]);
    uint32_t vdst = (uint32_t)__cvta_generic_to_shared(&smem[VS_OFF + buf * TILE_F]);
    const float* ks = g_K + (size_t)t * BN * SA_DH;
    const float* vs = g_V + (size_t)t * BN * SA_DH;
#pragma unroll
    for (int i = 0; i < 8; i++) {
        int c = tid + i * 256;          // 0..2047 16B-chunks
        int r = c >> 5, w = c & 31;     // row, 16B-chunk within row
        cp_async16(kdst + (uint32_t)(r * KPAD + w * 4) * 4, ks + r * SA_DH + w * 4);
        cp_async16(vdst + (uint32_t)(r * KPAD + w * 4) * 4, vs + r * SA_DH + w * 4);
    }
}

__global__ __launch_bounds__(256, 1)
void attn_kernel(float* __restrict__ out) {
    extern __shared__ float smem[];
    const int tid = threadIdx.x;
    const int ty = tid >> 4;   // 0..15  (4 query rows each)
    const int tx = tid & 15;   // 0..15
    const int row0 = blockIdx.x * BM;

    // --- load Q tile (pre-scaled in kernel 1) + prefetch chunk 0 ---
    {
        uint32_t qdst = (uint32_t)__cvta_generic_to_shared(&smem[QS_OFF]);
        const float* qs = g_Q + (size_t)row0 * SA_DH;
#pragma unroll
        for (int i = 0; i < 8; i++) {
            int c = tid + i * 256;
            int r = c >> 5, w = c & 31;
            cp_async16(qdst + (uint32_t)(r * KPAD + w * 4) * 4, qs + r * SA_DH + w * 4);
        }
        load_kv_chunk(smem, 0, 0, tid);
        cp_commit();
    }

    float o[4][8];
    float m[4], l[4];
#pragma unroll
    for (int rr = 0; rr < 4; rr++) {
        m[rr] = -INFINITY; l[rr] = 0.0f;
#pragma unroll
        for (int w = 0; w < 8; w++) o[rr][w] = 0.0f;
    }

    const int NCHUNK = SA_N / BN;   // 128
    for (int t = 0; t < NCHUNK; t++) {
        const int buf = t & 1;
        cp_wait0();
        __syncthreads();
        if (t + 1 < NCHUNK) {
            load_kv_chunk(smem, buf ^ 1, t + 1, tid);
            cp_commit();
        }

        const float* Kb = &smem[KS_OFF + buf * TILE_F];
        const float* Vb = &smem[VS_OFF + buf * TILE_F];
        const float* Qs = &smem[QS_OFF];

        // ----- S = Q K^T  (rows r=ty*4+rr, cols c=tx+cc*16) -----
        float s[4][4];
#pragma unroll
        for (int rr = 0; rr < 4; rr++)
#pragma unroll
            for (int cc = 0; cc < 4; cc++) s[rr][cc] = 0.0f;

#pragma unroll 8
        for (int k4 = 0; k4 < 32; k4++) {
            float qa[4][4], ka[4][4];
#pragma unroll
            for (int rr = 0; rr < 4; rr++) {
                float4 q = *(const float4*)&Qs[(ty * 4 + rr) * KPAD + k4 * 4];
                qa[rr][0] = q.x; qa[rr][1] = q.y; qa[rr][2] = q.z; qa[rr][3] = q.w;
            }
#pragma unroll
            for (int cc = 0; cc < 4; cc++) {
                float4 k = *(const float4*)&Kb[(tx + cc * 16) * KPAD + k4 * 4];
                ka[cc][0] = k.x; ka[cc][1] = k.y; ka[cc][2] = k.z; ka[cc][3] = k.w;
            }
#pragma unroll
            for (int rr = 0; rr < 4; rr++)
#pragma unroll
                for (int cc = 0; cc < 4; cc++)
#pragma unroll
                    for (int e = 0; e < 4; e++)
                        s[rr][cc] += qa[rr][e] * ka[cc][e];
        }

        // ----- online softmax (rows span 16 lanes of a half-warp) -----
#pragma unroll
        for (int rr = 0; rr < 4; rr++) {
            float mx = fmaxf(fmaxf(s[rr][0], s[rr][1]), fmaxf(s[rr][2], s[rr][3]));
#pragma unroll
            for (int d = 8; d >= 1; d >>= 1)
                mx = fmaxf(mx, __shfl_xor_sync(0xffffffffu, mx, d));
            float mn = fmaxf(m[rr], mx);
            float alpha = __expf(m[rr] - mn);
            m[rr] = mn;
            float rs = 0.0f;
#pragma unroll
            for (int cc = 0; cc < 4; cc++) {
                float p = __expf(s[rr][cc] - mn);
                s[rr][cc] = p;
                rs += p;
            }
#pragma unroll
            for (int d = 8; d >= 1; d >>= 1)
                rs += __shfl_xor_sync(0xffffffffu, rs, d);
            l[rr] = l[rr] * alpha + rs;
#pragma unroll
            for (int w = 0; w < 8; w++) o[rr][w] *= alpha;
            // stage P transposed: Ps[keycol][qrow]
#pragma unroll
            for (int cc = 0; cc < 4; cc++)
                smem[PS_OFF + (tx + cc * 16) * PPAD + ty * 4 + rr] = s[rr][cc];
        }
        __syncthreads();

        // ----- O += P V  (cols c=tx*8+w) -----
#pragma unroll 8
        for (int j = 0; j < BN; j++) {
            float4 pf = *(const float4*)&smem[PS_OFF + j * PPAD + ty * 4];
            float pv[4]; pv[0] = pf.x; pv[1] = pf.y; pv[2] = pf.z; pv[3] = pf.w;
            float4 a = *(const float4*)&Vb[j * KPAD + tx * 8];
            float4 b = *(const float4*)&Vb[j * KPAD + tx * 8 + 4];
            float vv[8];
            vv[0] = a.x; vv[1] = a.y; vv[2] = a.z; vv[3] = a.w;
            vv[4] = b.x; vv[5] = b.y; vv[6] = b.z; vv[7] = b.w;
#pragma unroll
            for (int rr = 0; rr < 4; rr++)
#pragma unroll
                for (int w = 0; w < 8; w++)
                    o[rr][w] += pv[rr] * vv[w];
        }
    }

    // ----- epilogue: O / l -----
#pragma unroll
    for (int rr = 0; rr < 4; rr++) {
        float inv = 1.0f / l[rr];
        size_t row = row0 + ty * 4 + rr;
        float4 o0, o1;
        o0.x = o[rr][0] * inv; o0.y = o[rr][1] * inv;
        o0.z = o[rr][2] * inv; o0.w = o[rr][3] * inv;
        o1.x = o[rr][4] * inv; o1.y = o[rr][5] * inv;
        o1.z = o[rr][6] * inv; o1.w = o[rr][7] * inv;
        *(float4*)&out[row * SA_DH + tx * 8]     = o0;
        *(float4*)&out[row * SA_DH + tx * 8 + 4] = o1;
    }
}

// ---------------------------------------------------------------------------
extern "C" void kernel_launch(void* const* d_in, const int* in_sizes, int n_in,
                              void* d_out, int out_size) {
    const float* x  = (const float*)d_in[0];
    const float* Wq = (const float*)d_in[1];
    const float* Wk = (const float*)d_in[2];
    const float* Wv = (const float*)d_in[3];
    float* out = (float*)d_out;

    cudaFuncSetAttribute(attn_kernel, cudaFuncAttributeMaxDynamicSharedMemorySize, SMEM_BYTES);

    qkv_kernel<<<dim3(SA_N / 64, 3), 256>>>(x, Wq, Wk, Wv);
    attn_kernel<<<SA_N / BM, 256, SMEM_BYTES>>>(out);
}

// round 2
// speedup vs baseline: 1.0019x; 1.0019x over previous
#include <cuda_runtime.h>
#include <cstdint>
#include <math.h>

#define SA_N  8192
#define SA_D  1024
#define SA_DH 128

#define BM 64
#define BN 64
#define KPAD 132           // row stride (floats) for Qs/Ks/Vs tiles (128 + 4)
#define PPAD 68            // row stride (floats) for Ps tile (64 + 4)

#define QS_OFF 0
#define TILE_F (BM*KPAD)   // 8448 floats per 64x128 tile
#define KS_OFF (TILE_F)
#define VS_OFF (TILE_F*3)
#define PS_OFF (TILE_F*5)
#define SMEM_FLOATS (TILE_F*5 + BN*PPAD)
#define SMEM_BYTES (SMEM_FLOATS*4)   // 186368 bytes

// Scratch for projected Q (pre-scaled), K, V
__device__ float g_Q[SA_N*SA_DH];
__device__ float g_K[SA_N*SA_DH];
__device__ float g_V[SA_N*SA_DH];

__device__ __forceinline__ void cp_async16(uint32_t dst, const void* src) {
    asm volatile("cp.async.cg.shared.global [%0], [%1], 16;\n" :: "r"(dst), "l"(src));
}
__device__ __forceinline__ void cp_commit() {
    asm volatile("cp.async.commit_group;\n" ::);
}
__device__ __forceinline__ void cp_wait0() {
    asm volatile("cp.async.wait_group 0;\n" ::);
}

// ---------------------------------------------------------------------------
// Kernel 1: QKV projection. grid = (N/64, 3), block = 256.
// Y = x @ W, Q additionally scaled by 1/sqrt(128).
// ---------------------------------------------------------------------------
#define P1_BK 32
__global__ __launch_bounds__(256, 1)
void qkv_kernel(const float* __restrict__ x,
                const float* __restrict__ Wq,
                const float* __restrict__ Wk,
                const float* __restrict__ Wv) {
    __shared__ float Xs[64][P1_BK + 4];
    __shared__ float Ws[P1_BK][SA_DH + 4];

    const float* W;
    float* Y;
    float scale;
    if (blockIdx.y == 0)      { W = Wq; Y = g_Q; scale = 0.08838834764831845f; }
    else if (blockIdx.y == 1) { W = Wk; Y = g_K; scale = 1.0f; }
    else                      { W = Wv; Y = g_V; scale = 1.0f; }

    const int tid = threadIdx.x;
    const int ty = tid >> 4;      // 0..15 -> 4 rows each
    const int tx = tid & 15;      // 0..15 -> 8 cols each
    const int row0 = blockIdx.x * 64;

    float acc[4][8];
#pragma unroll
    for (int r = 0; r < 4; r++)
#pragma unroll
        for (int c = 0; c < 8; c++) acc[r][c] = 0.0f;

    for (int k0 = 0; k0 < SA_D; k0 += P1_BK) {
        __syncthreads();
        // Xs: 64 x 32 floats = 512 float4, 2 per thread
#pragma unroll
        for (int i = tid; i < 64 * 8; i += 256) {
            int r = i >> 3, c4 = i & 7;
            float4 v = *(const float4*)&x[(size_t)(row0 + r) * SA_D + k0 + c4 * 4];
            *(float4*)&Xs[r][c4 * 4] = v;
        }
        // Ws: 32 x 128 floats = 1024 float4, 4 per thread
#pragma unroll
        for (int i = tid; i < 32 * 32; i += 256) {
            int r = i >> 5, c4 = i & 31;
            float4 v = *(const float4*)&W[(size_t)(k0 + r) * SA_DH + c4 * 4];
            *(float4*)&Ws[r][c4 * 4] = v;
        }
        __syncthreads();

#pragma unroll
        for (int kk4 = 0; kk4 < 8; kk4++) {
            float xa[4][4];
#pragma unroll
            for (int rr = 0; rr < 4; rr++) {
                float4 q = *(float4*)&Xs[ty * 4 + rr][kk4 * 4];
                xa[rr][0] = q.x; xa[rr][1] = q.y; xa[rr][2] = q.z; xa[rr][3] = q.w;
            }
#pragma unroll
            for (int kk = 0; kk < 4; kk++) {
                float4 w0 = *(float4*)&Ws[kk4 * 4 + kk][tx * 8];
                float4 w1 = *(float4*)&Ws[kk4 * 4 + kk][tx * 8 + 4];
                float wv[8];
                wv[0] = w0.x; wv[1] = w0.y; wv[2] = w0.z; wv[3] = w0.w;
                wv[4] = w1.x; wv[5] = w1.y; wv[6] = w1.z; wv[7] = w1.w;
#pragma unroll
                for (int rr = 0; rr < 4; rr++)
#pragma unroll
                    for (int c = 0; c < 8; c++)
                        acc[rr][c] += xa[rr][kk] * wv[c];
            }
        }
    }

#pragma unroll
    for (int rr = 0; rr < 4; rr++) {
        size_t row = row0 + ty * 4 + rr;
        float4 o0, o1;
        o0.x = acc[rr][0] * scale; o0.y = acc[rr][1] * scale;
        o0.z = acc[rr][2] * scale; o0.w = acc[rr][3] * scale;
        o1.x = acc[rr][4] * scale; o1.y = acc[rr][5] * scale;
        o1.z = acc[rr][6] * scale; o1.w = acc[rr][7] * scale;
        *(float4*)&Y[row * SA_DH + tx * 8]     = o0;
        *(float4*)&Y[row * SA_DH + tx * 8 + 4] = o1;
    }
}

// ---------------------------------------------------------------------------
// Kernel 2: fused flash attention (fp32). grid = N/64 = 128, block = 256.
// One CTA owns BM=64 query rows, streams all K/V in BN=64 chunks with
// cp.async double buffering, online softmax.
// ---------------------------------------------------------------------------
__device__ __forceinline__ void load_kv_chunk(float* smem, int buf, int t, int tid) {
    uint32_t kdst = (uint32_t)__cvta_generic_to_shared(&smem[KS_OFF + buf * TILE_F]);
    uint32_t vdst = (uint32_t)__cvta_generic_to_shared(&smem[VS_OFF + buf * TILE_F]);
    const float* ks = g_K + (size_t)t * BN * SA_DH;
    const float* vs = g_V + (size_t)t * BN * SA_DH;
#pragma unroll
    for (int i = 0; i < 8; i++) {
        int c = tid + i * 256;          // 0..2047 16B-chunks
        int r = c >> 5, w = c & 31;     // row, 16B-chunk within row
        cp_async16(kdst + (uint32_t)(r * KPAD + w * 4) * 4, ks + r * SA_DH + w * 4);
        cp_async16(vdst + (uint32_t)(r * KPAD + w * 4) * 4, vs + r * SA_DH + w * 4);
    }
}

__global__ __launch_bounds__(256, 1)
void attn_kernel(float* __restrict__ out) {
    extern __shared__ float smem[];
    const int tid = threadIdx.x;
    const int ty = tid >> 4;   // 0..15  (4 query rows each)
    const int tx = tid & 15;   // 0..15
    const int row0 = blockIdx.x * BM;

    // --- load Q tile (pre-scaled in kernel 1) + prefetch chunk 0 ---
    {
        uint32_t qdst = (uint32_t)__cvta_generic_to_shared(&smem[QS_OFF]);
        const float* qs = g_Q + (size_t)row0 * SA_DH;
#pragma unroll
        for (int i = 0; i < 8; i++) {
            int c = tid + i * 256;
            int r = c >> 5, w = c & 31;
            cp_async16(qdst + (uint32_t)(r * KPAD + w * 4) * 4, qs + r * SA_DH + w * 4);
        }
        load_kv_chunk(smem, 0, 0, tid);
        cp_commit();
    }

    float o[4][8];
    float m[4], l[4];
#pragma unroll
    for (int rr = 0; rr < 4; rr++) {
        m[rr] = -INFINITY; l[rr] = 0.0f;
#pragma unroll
        for (int w = 0; w < 8; w++) o[rr][w] = 0.0f;
    }

    const int NCHUNK = SA_N / BN;   // 128
    for (int t = 0; t < NCHUNK; t++) {
        const int buf = t & 1;
        cp_wait0();
        __syncthreads();
        if (t + 1 < NCHUNK) {
            load_kv_chunk(smem, buf ^ 1, t + 1, tid);
            cp_commit();
        }

        const float* Kb = &smem[KS_OFF + buf * TILE_F];
        const float* Vb = &smem[VS_OFF + buf * TILE_F];
        const float* Qs = &smem[QS_OFF];

        // ----- S = Q K^T  (rows r=ty*4+rr, cols c=tx+cc*16) -----
        float s[4][4];
#pragma unroll
        for (int rr = 0; rr < 4; rr++)
#pragma unroll
            for (int cc = 0; cc < 4; cc++) s[rr][cc] = 0.0f;

#pragma unroll 8
        for (int k4 = 0; k4 < 32; k4++) {
            float qa[4][4], ka[4][4];
#pragma unroll
            for (int rr = 0; rr < 4; rr++) {
                float4 q = *(const float4*)&Qs[(ty * 4 + rr) * KPAD + k4 * 4];
                qa[rr][0] = q.x; qa[rr][1] = q.y; qa[rr][2] = q.z; qa[rr][3] = q.w;
            }
#pragma unroll
            for (int cc = 0; cc < 4; cc++) {
                float4 k = *(const float4*)&Kb[(tx + cc * 16) * KPAD + k4 * 4];
                ka[cc][0] = k.x; ka[cc][1] = k.y; ka[cc][2] = k.z; ka[cc][3] = k.w;
            }
#pragma unroll
            for (int rr = 0; rr < 4; rr++)
#pragma unroll
                for (int cc = 0; cc < 4; cc++)
#pragma unroll
                    for (int e = 0; e < 4; e++)
                        s[rr][cc] += qa[rr][e] * ka[cc][e];
        }

        // ----- online softmax (rows span 16 lanes of a half-warp) -----
#pragma unroll
        for (int rr = 0; rr < 4; rr++) {
            float mx = fmaxf(fmaxf(s[rr][0], s[rr][1]), fmaxf(s[rr][2], s[rr][3]));
#pragma unroll
            for (int d = 8; d >= 1; d >>= 1)
                mx = fmaxf(mx, __shfl_xor_sync(0xffffffffu, mx, d));
            float mn = fmaxf(m[rr], mx);
            float alpha = __expf(m[rr] - mn);
            m[rr] = mn;
            float rs = 0.0f;
#pragma unroll
            for (int cc = 0; cc < 4; cc++) {
                float p = __expf(s[rr][cc] - mn);
                s[rr][cc] = p;
                rs += p;
            }
#pragma unroll
            for (int d = 8; d >= 1; d >>= 1)
                rs += __shfl_xor_sync(0xffffffffu, rs, d);
            l[rr] = l[rr] * alpha + rs;
#pragma unroll
            for (int w = 0; w < 8; w++) o[rr][w] *= alpha;
            // stage P transposed: Ps[keycol][qrow]
#pragma unroll
            for (int cc = 0; cc < 4; cc++)
                smem[PS_OFF + (tx + cc * 16) * PPAD + ty * 4 + rr] = s[rr][cc];
        }
        __syncthreads();

        // ----- O += P V  (cols c=tx*8+w) -----
#pragma unroll 8
        for (int j = 0; j < BN; j++) {
            float4 pf = *(const float4*)&smem[PS_OFF + j * PPAD + ty * 4];
            float pv[4]; pv[0] = pf.x; pv[1] = pf.y; pv[2] = pf.z; pv[3] = pf.w;
            float4 a = *(const float4*)&Vb[j * KPAD + tx * 8];
            float4 b = *(const float4*)&Vb[j * KPAD + tx * 8 + 4];
            float vv[8];
            vv[0] = a.x; vv[1] = a.y; vv[2] = a.z; vv[3] = a.w;
            vv[4] = b.x; vv[5] = b.y; vv[6] = b.z; vv[7] = b.w;
#pragma unroll
            for (int rr = 0; rr < 4; rr++)
#pragma unroll
                for (int w = 0; w < 8; w++)
                    o[rr][w] += pv[rr] * vv[w];
        }
    }

    // ----- epilogue: O / l -----
#pragma unroll
    for (int rr = 0; rr < 4; rr++) {
        float inv = 1.0f / l[rr];
        size_t row = row0 + ty * 4 + rr;
        float4 o0, o1;
        o0.x = o[rr][0] * inv; o0.y = o[rr][1] * inv;
        o0.z = o[rr][2] * inv; o0.w = o[rr][3] * inv;
        o1.x = o[rr][4] * inv; o1.y = o[rr][5] * inv;
        o1.z = o[rr][6] * inv; o1.w = o[rr][7] * inv;
        *(float4*)&out[row * SA_DH + tx * 8]     = o0;
        *(float4*)&out[row * SA_DH + tx * 8 + 4] = o1;
    }
}

// ---------------------------------------------------------------------------
extern "C" void kernel_launch(void* const* d_in, const int* in_sizes, int n_in,
                              void* d_out, int out_size) {
    const float* x  = (const float*)d_in[0];
    const float* Wq = (const float*)d_in[1];
    const float* Wk = (const float*)d_in[2];
    const float* Wv = (const float*)d_in[3];
    float* out = (float*)d_out;

    cudaFuncSetAttribute(attn_kernel, cudaFuncAttributeMaxDynamicSharedMemorySize, SMEM_BYTES);

    qkv_kernel<<<dim3(SA_N / 64, 3), 256>>>(x, Wq, Wk, Wv);
    attn_kernel<<<SA_N / BM, 256, SMEM_BYTES>>>(out);
}

// round 3
// speedup vs baseline: 1.3215x; 1.3190x over previous
#include <cuda_runtime.h>
#include <cstdint>
#include <math.h>

typedef unsigned long long u64;

#define SA_N  8192
#define SA_D  1024
#define SA_DH 128

#define BM 64
#define BN 64
#define QPAD 132          // Q tile row stride (floats)
#define KPADK 130         // K tile row stride: 130 ≡ 2 mod 32 banks -> conflict-free stride-1-row access
#define VPAD 132          // V tile row stride
#define PPAD 68           // P tile row stride

// smem layout (floats)
#define QS_OFF 0
#define KS_OFF 8448                  // 64*132
#define KTILE  8320                  // 64*130
#define VS_OFF (KS_OFF + 2*KTILE)    // 25088
#define VTILE  8448                  // 64*132
#define PS_OFF (VS_OFF + 2*VTILE)    // 41984
#define SMEM_FLOATS (PS_OFF + 64*PPAD)   // 46336
#define SMEM_BYTES (SMEM_FLOATS*4)       // 185344

__device__ float g_Q[SA_N*SA_DH];
__device__ float g_K[SA_N*SA_DH];
__device__ float g_V[SA_N*SA_DH];

// ---- f32x2 packed math (Blackwell) --------------------------------------
__device__ __forceinline__ void ffma2(u64& d, u64 a, u64 b) {
    asm("fma.rn.f32x2 %0, %1, %2, %0;" : "+l"(d) : "l"(a), "l"(b));
}
__device__ __forceinline__ u64 pack2(float x) {
    u64 d; asm("mov.b64 %0, {%1, %1};" : "=l"(d) : "f"(x)); return d;
}
__device__ __forceinline__ float2 unpack2(u64 d) {
    float2 f; asm("mov.b64 {%0, %1}, %2;" : "=f"(f.x), "=f"(f.y) : "l"(d)); return f;
}
__device__ __forceinline__ void fmul2(u64& d, u64 a) {
    asm("mul.rn.f32x2 %0, %0, %1;" : "+l"(d) : "l"(a));
}

// ---- cp.async -----------------------------------------------------------
__device__ __forceinline__ void cp_async16(uint32_t dst, const void* src) {
    asm volatile("cp.async.cg.shared.global [%0], [%1], 16;\n" :: "r"(dst), "l"(src));
}
__device__ __forceinline__ void cp_async8(uint32_t dst, const void* src) {
    asm volatile("cp.async.ca.shared.global [%0], [%1], 8;\n" :: "r"(dst), "l"(src));
}
__device__ __forceinline__ void cp_commit() { asm volatile("cp.async.commit_group;\n" ::); }
__device__ __forceinline__ void cp_wait0()  { asm volatile("cp.async.wait_group 0;\n" ::); }

// ---------------------------------------------------------------------------
// Kernel 1: QKV projection with FFMA2 (col-paired). grid=(N/64,3), block=256.
// ---------------------------------------------------------------------------
#define P1_BK 32
__global__ __launch_bounds__(256, 1)
void qkv_kernel(const float* __restrict__ x,
                const float* __restrict__ Wq,
                const float* __restrict__ Wk,
                const float* __restrict__ Wv) {
    __shared__ float Xs[64][P1_BK + 4];
    __shared__ float Ws[P1_BK][SA_DH + 4];

    const float* W; float* Y; float scale;
    if (blockIdx.y == 0)      { W = Wq; Y = g_Q; scale = 0.08838834764831845f; }
    else if (blockIdx.y == 1) { W = Wk; Y = g_K; scale = 1.0f; }
    else                      { W = Wv; Y = g_V; scale = 1.0f; }

    const int tid = threadIdx.x;
    const int ty = tid >> 4;      // 4 rows each
    const int tx = tid & 15;      // cols 2tx+32p (+1)
    const int row0 = blockIdx.x * 64;

    u64 acc2[4][4];
#pragma unroll
    for (int r = 0; r < 4; r++)
#pragma unroll
        for (int p = 0; p < 4; p++) acc2[r][p] = 0ull;

    for (int k0 = 0; k0 < SA_D; k0 += P1_BK) {
        __syncthreads();
#pragma unroll
        for (int i = tid; i < 64 * 8; i += 256) {
            int r = i >> 3, c4 = i & 7;
            float4 v = *(const float4*)&x[(size_t)(row0 + r) * SA_D + k0 + c4 * 4];
            *(float4*)&Xs[r][c4 * 4] = v;
        }
#pragma unroll
        for (int i = tid; i < 32 * 32; i += 256) {
            int r = i >> 5, c4 = i & 31;
            float4 v = *(const float4*)&W[(size_t)(k0 + r) * SA_DH + c4 * 4];
            *(float4*)&Ws[r][c4 * 4] = v;
        }
        __syncthreads();

#pragma unroll 8
        for (int kk = 0; kk < P1_BK; kk++) {
            u64 xd[4], w2[4];
#pragma unroll
            for (int rr = 0; rr < 4; rr++) xd[rr] = pack2(Xs[ty * 4 + rr][kk]);
#pragma unroll
            for (int p = 0; p < 4; p++)
                w2[p] = *(const u64*)&Ws[kk][tx * 2 + p * 32];
#pragma unroll
            for (int rr = 0; rr < 4; rr++)
#pragma unroll
                for (int p = 0; p < 4; p++)
                    ffma2(acc2[rr][p], xd[rr], w2[p]);
        }
    }

#pragma unroll
    for (int rr = 0; rr < 4; rr++) {
        size_t row = row0 + ty * 4 + rr;
#pragma unroll
        for (int p = 0; p < 4; p++) {
            float2 f = unpack2(acc2[rr][p]);
            f.x *= scale; f.y *= scale;
            *(float2*)&Y[row * SA_DH + tx * 2 + p * 32] = f;
        }
    }
}

// ---------------------------------------------------------------------------
// Kernel 2: fused flash attention, FFMA2 everywhere. grid=128, block=256.
// ---------------------------------------------------------------------------
__device__ __forceinline__ void load_kv_chunk(float* smem, int buf, int t, int tid) {
    uint32_t kdst = (uint32_t)__cvta_generic_to_shared(&smem[KS_OFF + buf * KTILE]);
    uint32_t vdst = (uint32_t)__cvta_generic_to_shared(&smem[VS_OFF + buf * VTILE]);
    const float* ks = g_K + (size_t)t * BN * SA_DH;
    const float* vs = g_V + (size_t)t * BN * SA_DH;
    // K: 64x128 floats as 4096 8B words (row stride 130 floats = 520B, 8B-aligned)
#pragma unroll
    for (int i = 0; i < 16; i++) {
        int c = tid + i * 256;
        int r = c >> 6, w = c & 63;
        cp_async8(kdst + (uint32_t)(r * KPADK + w * 2) * 4, ks + r * SA_DH + w * 2);
    }
    // V: 64x128 floats as 2048 16B words
#pragma unroll
    for (int i = 0; i < 8; i++) {
        int c = tid + i * 256;
        int r = c >> 5, w = c & 31;
        cp_async16(vdst + (uint32_t)(r * VPAD + w * 4) * 4, vs + r * SA_DH + w * 4);
    }
}

__global__ __launch_bounds__(256, 1)
void attn_kernel(float* __restrict__ out) {
    extern __shared__ float smem[];
    const int tid = threadIdx.x;
    const int ty = tid >> 4;   // 4 query rows each
    const int tx = tid & 15;
    const int row0 = blockIdx.x * BM;

    // Q tile + first K/V chunk
    {
        uint32_t qdst = (uint32_t)__cvta_generic_to_shared(&smem[QS_OFF]);
        const float* qs = g_Q + (size_t)row0 * SA_DH;
#pragma unroll
        for (int i = 0; i < 8; i++) {
            int c = tid + i * 256;
            int r = c >> 5, w = c & 31;
            cp_async16(qdst + (uint32_t)(r * QPAD + w * 4) * 4, qs + r * SA_DH + w * 4);
        }
        load_kv_chunk(smem, 0, 0, tid);
        cp_commit();
    }

    u64 o2[4][4];              // rows rr, col-pairs (2tx+32u, +1)
    float m[4], l[4];
#pragma unroll
    for (int rr = 0; rr < 4; rr++) {
        m[rr] = -INFINITY; l[rr] = 0.0f;
#pragma unroll
        for (int u = 0; u < 4; u++) o2[rr][u] = 0ull;
    }

    const int NCHUNK = SA_N / BN;   // 128
    for (int t = 0; t < NCHUNK; t++) {
        const int buf = t & 1;
        cp_wait0();
        __syncthreads();
        if (t + 1 < NCHUNK) {
            load_kv_chunk(smem, buf ^ 1, t + 1, tid);
            cp_commit();
        }

        const float* Kb = &smem[KS_OFF + buf * KTILE];
        const float* Vb = &smem[VS_OFF + buf * VTILE];

        // ----- S = Q K^T : k-paired FFMA2, dual partial sums -----
        u64 s2[4][4];
#pragma unroll
        for (int rr = 0; rr < 4; rr++)
#pragma unroll
            for (int cc = 0; cc < 4; cc++) s2[rr][cc] = 0ull;

#pragma unroll 8
        for (int k4 = 0; k4 < 32; k4++) {      // 4 k-elems = 2 k-pairs per iter
            u64 q0[4], q1[4], kk0[4], kk1[4];
#pragma unroll
            for (int rr = 0; rr < 4; rr++) {
                ulonglong2 qv = *(const ulonglong2*)&smem[QS_OFF + (ty * 4 + rr) * QPAD + k4 * 4];
                q0[rr] = qv.x; q1[rr] = qv.y;
            }
#pragma unroll
            for (int cc = 0; cc < 4; cc++) {
                kk0[cc] = *(const u64*)&Kb[(tx + cc * 16) * KPADK + k4 * 4];
                kk1[cc] = *(const u64*)&Kb[(tx + cc * 16) * KPADK + k4 * 4 + 2];
            }
#pragma unroll
            for (int rr = 0; rr < 4; rr++)
#pragma unroll
                for (int cc = 0; cc < 4; cc++) {
                    ffma2(s2[rr][cc], q0[rr], kk0[cc]);
                    ffma2(s2[rr][cc], q1[rr], kk1[cc]);
                }
        }

        // ----- online softmax -----
#pragma unroll
        for (int rr = 0; rr < 4; rr++) {
            float sv[4];
#pragma unroll
            for (int cc = 0; cc < 4; cc++) {
                float2 f = unpack2(s2[rr][cc]);
                sv[cc] = f.x + f.y;
            }
            float mx = fmaxf(fmaxf(sv[0], sv[1]), fmaxf(sv[2], sv[3]));
#pragma unroll
            for (int d = 8; d >= 1; d >>= 1)
                mx = fmaxf(mx, __shfl_xor_sync(0xffffffffu, mx, d));
            float mn = fmaxf(m[rr], mx);
            float alpha = __expf(m[rr] - mn);
            m[rr] = mn;
            float rs = 0.0f;
#pragma unroll
            for (int cc = 0; cc < 4; cc++) {
                float p = __expf(sv[cc] - mn);
                sv[cc] = p;
                rs += p;
            }
#pragma unroll
            for (int d = 8; d >= 1; d >>= 1)
                rs += __shfl_xor_sync(0xffffffffu, rs, d);
            l[rr] = l[rr] * alpha + rs;
            u64 ad = pack2(alpha);
#pragma unroll
            for (int u = 0; u < 4; u++) fmul2(o2[rr][u], ad);
#pragma unroll
            for (int cc = 0; cc < 4; cc++)
                smem[PS_OFF + (ty * 4 + rr) * PPAD + tx + cc * 16] = sv[cc];
        }
        __syncthreads();

        // ----- O += P V : col-paired FFMA2 -----
#pragma unroll 4
        for (int j4 = 0; j4 < 16; j4++) {      // 4 keys per iter
            float pr[4][4];
#pragma unroll
            for (int rr = 0; rr < 4; rr++) {
                float4 pf = *(const float4*)&smem[PS_OFF + (ty * 4 + rr) * PPAD + j4 * 4];
                pr[rr][0] = pf.x; pr[rr][1] = pf.y; pr[rr][2] = pf.z; pr[rr][3] = pf.w;
            }
#pragma unroll
            for (int jj = 0; jj < 4; jj++) {
                u64 vv[4];
#pragma unroll
                for (int u = 0; u < 4; u++)
                    vv[u] = *(const u64*)&Vb[(j4 * 4 + jj) * VPAD + tx * 2 + u * 32];
#pragma unroll
                for (int rr = 0; rr < 4; rr++) {
                    u64 pd = pack2(pr[rr][jj]);
#pragma unroll
                    for (int u = 0; u < 4; u++)
                        ffma2(o2[rr][u], pd, vv[u]);
                }
            }
        }
    }

    // ----- epilogue -----
#pragma unroll
    for (int rr = 0; rr < 4; rr++) {
        float inv = 1.0f / l[rr];
        size_t row = row0 + ty * 4 + rr;
#pragma unroll
        for (int u = 0; u < 4; u++) {
            float2 f = unpack2(o2[rr][u]);
            f.x *= inv; f.y *= inv;
            *(float2*)&out[row * SA_DH + tx * 2 + u * 32] = f;
        }
    }
}

// ---------------------------------------------------------------------------
extern "C" void kernel_launch(void* const* d_in, const int* in_sizes, int n_in,
                              void* d_out, int out_size) {
    const float* x  = (const float*)d_in[0];
    const float* Wq = (const float*)d_in[1];
    const float* Wk = (const float*)d_in[2];
    const float* Wv = (const float*)d_in[3];
    float* out = (float*)d_out;

    cudaFuncSetAttribute(attn_kernel, cudaFuncAttributeMaxDynamicSharedMemorySize, SMEM_BYTES);

    qkv_kernel<<<dim3(SA_N / 64, 3), 256>>>(x, Wq, Wk, Wv);
    attn_kernel<<<SA_N / BM, 256, SMEM_BYTES>>>(out);
}